// round 2
// baseline (speedup 1.0000x reference)
#include <cuda_runtime.h>
#include <stdint.h>

// Problem constants
#define BB 16
#define DD 256
#define TT 2048
#define KK 8192
#define NN (BB*TT)            // 32768 tokens
#define OUTQ (BB*DD*TT)       // 8388608 floats of quantized_st
// Output layout: [quantized_st (OUTQ)][loss (1)][idx (NN)]

#define TM   32               // tokens per block
#define TKC  256              // codes per kc chunk
#define DK   32               // d-slice
#define ESTRIDE 258           // es row stride (floats): 8B-aligned rows, 2-way store conflicts
#define ZS2_BYTES (256*32*8)                  // 65536
#define ES_BYTES  (2*DK*ESTRIDE*4)            // 66048
#define SB_BYTES  (8*32*8)                    // 2048
#define SMEM_TOTAL (ZS2_BYTES + ES_BYTES + SB_BYTES)

__device__ float g_enorm[KK];
__device__ float g_rnorm[NN];
__device__ int   g_idx[NN];
__device__ float g_loss;

// ---------------------------------------------------------------------------
// enorm[k] = sum_d emb[k][d]^2  (one warp per code)
// ---------------------------------------------------------------------------
__global__ void k_enorm(const float* __restrict__ emb) {
    int gw = (blockIdx.x * blockDim.x + threadIdx.x) >> 5;
    int lane = threadIdx.x & 31;
    if (gw >= KK) return;
    const float* row = emb + (size_t)gw * DD;
    float s = 0.f;
    #pragma unroll
    for (int i = 0; i < 8; i++) {
        float v = row[lane + 32 * i];
        s = __fadd_rn(s, __fmul_rn(v, v));
    }
    #pragma unroll
    for (int o = 16; o; o >>= 1) s = __fadd_rn(s, __shfl_down_sync(0xffffffffu, s, o));
    if (lane == 0) g_enorm[gw] = s;
}

// ---------------------------------------------------------------------------
// rnorm[n] = sum_d z[b][d][t]^2  (warp row-reduce, same order as round 1)
// ---------------------------------------------------------------------------
__global__ void k_rnorm(const float* __restrict__ z) {
    int n = (blockIdx.x * blockDim.x + threadIdx.x) >> 5;
    int lane = threadIdx.x & 31;
    if (n >= NN) return;
    int b = n >> 11, t = n & (TT - 1);
    const float* zp = z + (size_t)b * DD * TT + t;
    float s = 0.f;
    #pragma unroll
    for (int i = 0; i < 8; i++) {
        float v = zp[(size_t)(lane + 32 * i) * TT];
        s = __fadd_rn(s, __fmul_rn(v, v));
    }
    #pragma unroll
    for (int o = 16; o; o >>= 1) s = __fadd_rn(s, __shfl_down_sync(0xffffffffu, s, o));
    if (lane == 0) g_rnorm[n] = s;
}

__global__ void k_zero() { g_loss = 0.f; }

// ---------------------------------------------------------------------------
// Argmin "GEMM", round 2:
//  - block tile 32 tokens x 256 codes; warp tile 32 tokens x 32 codes
//  - thread: 4 tokens x 8 codes (adjacent code pairs as f32x2)
//  - z duplicated once into smem (zs2), e staged per 32-d slice, double-buffered
//  - FFMA2 inner product; rounding chain identical to reference:
//      dist = fl( fl(rnorm + enorm) - fl(2 * dot) ), dot accumulated d-ascending
// ---------------------------------------------------------------------------
__global__ __launch_bounds__(256, 1) void k_argmin(
    const float* __restrict__ z, const float* __restrict__ emb,
    float* __restrict__ out, int write_idx)
{
    extern __shared__ char smem_raw[];
    float2* zs2 = (float2*)smem_raw;                                // [256][32] duplicated z
    float*  es  = (float*)(smem_raw + ZS2_BYTES);                   // [2][DK][ESTRIDE]
    unsigned long long* sbest = (unsigned long long*)(smem_raw + ZS2_BYTES + ES_BYTES); // [8][32]

    const int tid  = threadIdx.x;
    const int lane = tid & 31;
    const int wq   = tid >> 5;         // warp 0..7 -> code strip [32*wq, 32*wq+32)
    const int lx   = lane & 3;         // code subgroup (8 codes)
    const int ly   = lane >> 2;        // token group (4 tokens)
    const int k2   = lane >> 3;        // staging: k sub-index 0..3
    const int dd8  = lane & 7;         // staging: d quad index 0..7
    const int m0   = blockIdx.x * TM;
    const int b    = m0 >> 11, t0 = m0 & (TT - 1);
    const float* zb = z + (size_t)b * DD * TT + t0;
    const int cbase = wq * 32 + lx * 8;

    // ---- stage duplicated z once: zs2[d][t] = (z, z) ----
    #pragma unroll 4
    for (int it = 0; it < 32; it++) {
        int d = (tid >> 5) + 8 * it;
        float v = zb[(size_t)d * TT + (tid & 31)];
        zs2[d * 32 + (tid & 31)] = make_float2(v, v);
    }

    float rrow[4];
    #pragma unroll
    for (int t = 0; t < 4; t++) rrow[t] = g_rnorm[m0 + ly * 4 + t];

    unsigned long long best[4];
    #pragma unroll
    for (int t = 0; t < 4; t++) best[t] = ~0ull;

    unsigned long long acc[4][4];
    float4 pf[8];

    // ---- prologue: load + store slice 0 ----
    #pragma unroll
    for (int it = 0; it < 8; it++) {
        int k = wq * 32 + it * 4 + k2;
        pf[it] = *(const float4*)(emb + (size_t)k * DD + dd8 * 4);
    }
    {
        float* eb = es;   // buffer 0
        #pragma unroll
        for (int it = 0; it < 8; it++) {
            int k = wq * 32 + it * 4 + k2;
            float* ep = eb + (dd8 * 4) * ESTRIDE + k;
            ep[0 * ESTRIDE] = pf[it].x;
            ep[1 * ESTRIDE] = pf[it].y;
            ep[2 * ESTRIDE] = pf[it].z;
            ep[3 * ESTRIDE] = pf[it].w;
        }
    }
    __syncthreads();

    #pragma unroll 1
    for (int s = 0; s < 256; s++) {
        const int kc = s >> 3;
        const int ds = (s & 7) * 32;

        if ((s & 7) == 0) {
            #pragma unroll
            for (int t = 0; t < 4; t++)
                #pragma unroll
                for (int j = 0; j < 4; j++) acc[t][j] = 0ull;
        }

        // prefetch next slice into registers (latency hidden by compute)
        const int sn = s + 1;
        if (sn < 256) {
            const int kcn = sn >> 3, dsn = (sn & 7) * 32;
            #pragma unroll
            for (int it = 0; it < 8; it++) {
                int k = wq * 32 + it * 4 + k2;
                pf[it] = *(const float4*)(emb + (size_t)(kcn * TKC + k) * DD + dsn + dd8 * 4);
            }
        }

        // ---- compute current slice ----
        const float* eb = es + (s & 1) * (DK * ESTRIDE);
        #pragma unroll
        for (int dd = 0; dd < DK; dd++) {
            const float* ep = eb + dd * ESTRIDE + cbase;
            unsigned long long e0 = *(const unsigned long long*)(ep + 0);
            unsigned long long e1 = *(const unsigned long long*)(ep + 2);
            unsigned long long e2 = *(const unsigned long long*)(ep + 4);
            unsigned long long e3 = *(const unsigned long long*)(ep + 6);
            const ulonglong2* zp = (const ulonglong2*)(zs2 + (ds + dd) * 32 + ly * 4);
            ulonglong2 za = zp[0];
            ulonglong2 zb2 = zp[1];
            unsigned long long zz[4] = { za.x, za.y, zb2.x, zb2.y };
            #pragma unroll
            for (int t = 0; t < 4; t++) {
                asm("fma.rn.f32x2 %0, %1, %2, %0;" : "+l"(acc[t][0]) : "l"(zz[t]), "l"(e0));
                asm("fma.rn.f32x2 %0, %1, %2, %0;" : "+l"(acc[t][1]) : "l"(zz[t]), "l"(e1));
                asm("fma.rn.f32x2 %0, %1, %2, %0;" : "+l"(acc[t][2]) : "l"(zz[t]), "l"(e2));
                asm("fma.rn.f32x2 %0, %1, %2, %0;" : "+l"(acc[t][3]) : "l"(zz[t]), "l"(e3));
            }
        }

        // store prefetched slice into the other buffer
        if (sn < 256) {
            float* ebn = es + (sn & 1) * (DK * ESTRIDE);
            #pragma unroll
            for (int it = 0; it < 8; it++) {
                int k = wq * 32 + it * 4 + k2;
                float* ep = ebn + (dd8 * 4) * ESTRIDE + k;
                ep[0 * ESTRIDE] = pf[it].x;
                ep[1 * ESTRIDE] = pf[it].y;
                ep[2 * ESTRIDE] = pf[it].z;
                ep[3 * ESTRIDE] = pf[it].w;
            }
        }
        __syncthreads();

        // ---- epilogue per kc chunk: distances + argmin update ----
        if ((s & 7) == 7) {
            #pragma unroll
            for (int j = 0; j < 4; j++) {
                int c0 = kc * TKC + cbase + 2 * j;
                float en0 = g_enorm[c0], en1 = g_enorm[c0 + 1];
                #pragma unroll
                for (int t = 0; t < 4; t++) {
                    float slo = __uint_as_float((unsigned)(acc[t][j] & 0xffffffffull));
                    float shi = __uint_as_float((unsigned)(acc[t][j] >> 32));
                    float d0 = __fsub_rn(__fadd_rn(rrow[t], en0), __fmul_rn(2.0f, slo));
                    float d1 = __fsub_rn(__fadd_rn(rrow[t], en1), __fmul_rn(2.0f, shi));
                    unsigned long long p0 =
                        ((unsigned long long)__float_as_uint(d0) << 32) | (unsigned)c0;
                    unsigned long long p1 =
                        ((unsigned long long)__float_as_uint(d1) << 32) | (unsigned)(c0 + 1);
                    if (p0 < best[t]) best[t] = p0;
                    if (p1 < best[t]) best[t] = p1;
                }
            }
        }
    }

    // ---- reduce across lx lanes (same tokens, different codes) ----
    #pragma unroll
    for (int t = 0; t < 4; t++) {
        unsigned long long p = best[t];
        unsigned long long q;
        q = __shfl_xor_sync(0xffffffffu, p, 1); if (q < p) p = q;
        q = __shfl_xor_sync(0xffffffffu, p, 2); if (q < p) p = q;
        if (lx == 0) sbest[wq * 32 + ly * 4 + t] = p;
    }
    __syncthreads();

    // ---- reduce across warps; write idx ----
    if (tid < 32) {
        unsigned long long p = sbest[tid];
        #pragma unroll
        for (int w = 1; w < 8; w++) {
            unsigned long long q = sbest[w * 32 + tid];
            if (q < p) p = q;
        }
        int kb = (int)(p & 0xffffffffull);
        int n = m0 + tid;
        g_idx[n] = kb;
        if (write_idx) out[(size_t)OUTQ + 1 + n] = (float)kb;
    }
}

// ---------------------------------------------------------------------------
// Gather quantized output + loss partial sums (unchanged from round 1)
// ---------------------------------------------------------------------------
__global__ void k_gather(const float* __restrict__ z, const float* __restrict__ emb,
                         float* __restrict__ out) {
    __shared__ int sk[32];
    __shared__ float red[8];
    int m0 = blockIdx.x * 32;
    int b = m0 >> 11, t0 = m0 & (TT - 1);
    int tid = threadIdx.x;
    if (tid < 32) sk[tid] = g_idx[m0 + tid];
    __syncthreads();
    int tt = tid & 31, dg = tid >> 5;
    size_t base = (size_t)b * DD * TT + t0 + tt;
    const float* erow = emb + (size_t)sk[tt] * DD;
    float s = 0.f;
    #pragma unroll
    for (int l = 0; l < 32; l++) {
        int d = dg * 32 + l;
        float q  = erow[d];
        float zv = z[base + (size_t)d * TT];
        float df = __fsub_rn(q, zv);
        out[base + (size_t)d * TT] = __fadd_rn(zv, df);
        s = __fmaf_rn(df, df, s);
    }
    #pragma unroll
    for (int o = 16; o; o >>= 1) s += __shfl_xor_sync(0xffffffffu, s, o);
    if ((tid & 31) == 0) red[tid >> 5] = s;
    __syncthreads();
    if (tid < 8) {
        s = red[tid];
        #pragma unroll
        for (int o = 4; o; o >>= 1) s += __shfl_xor_sync(0x000000ffu, s, o);
        if (tid == 0) atomicAdd(&g_loss, s);
    }
}

__global__ void k_final(float* __restrict__ out, int write_loss) {
    if (write_loss) {
        float m = g_loss / (float)OUTQ;           // mean((q - z)^2)
        out[OUTQ] = __fmul_rn(1.25f, m);          // q_loss + 0.25 * e_loss
    }
}

// ---------------------------------------------------------------------------
extern "C" void kernel_launch(void* const* d_in, const int* in_sizes, int n_in,
                              void* d_out, int out_size) {
    const float* z   = (const float*)d_in[0];   // [B, D, T]
    const float* emb = (const float*)d_in[1];   // [K, D]
    float* out = (float*)d_out;

    int write_idx  = (out_size >= OUTQ + 1 + NN) ? 1 : 0;
    int write_loss = (out_size >= OUTQ + 1) ? 1 : 0;

    cudaFuncSetAttribute(k_argmin, cudaFuncAttributeMaxDynamicSharedMemorySize, SMEM_TOTAL);

    k_enorm <<<KK / 8, 256>>>(emb);
    k_rnorm <<<NN / 8, 256>>>(z);
    k_zero  <<<1, 1>>>();
    k_argmin<<<NN / TM, 256, SMEM_TOTAL>>>(z, emb, out, write_idx);
    k_gather<<<NN / 32, 256>>>(z, emb, out);
    k_final <<<1, 1>>>(out, write_loss);
}